// round 4
// baseline (speedup 1.0000x reference)
#include <cuda_runtime.h>
#include <cuda_bf16.h>
#include <math.h>

// Problem constants: B=4, T=2048, C=1024, H=16, D=64
#define BB 4
#define TT 2048
#define CC 1024
#define HH 16
#define DD 64
#define MM (BB*TT)        // 8192
#define C3 (3*CC)         // 3072

// ------------------------------------------------------------------
// Scratch
// ------------------------------------------------------------------
__device__ float g_qkv[(size_t)MM*C3];     // [B,T,3C] fp32
__device__ float g_q[(size_t)MM*CC];       // [B,H,T,D] roped, tf32
__device__ float g_k[(size_t)MM*CC];       // [B,H,T,D] roped, tf32
__device__ float g_v[(size_t)MM*CC];       // [B,H,T,D] tf32
__device__ float g_y[(size_t)MM*CC];       // attn out [B,T,C], tf32
__device__ float g_xt[(size_t)MM*CC];      // x rounded to tf32
__device__ float g_wq[(size_t)CC*C3];      // w_qkv tf32
__device__ float g_wp[(size_t)CC*CC];      // w_proj tf32
__device__ float g_cos[TT*32];
__device__ float g_sin[TT*32];

// ------------------------------------------------------------------
// helpers
// ------------------------------------------------------------------
__device__ __forceinline__ float f2tf32(float x) {
    unsigned r;
    asm("cvt.rna.tf32.f32 %0, %1;" : "=r"(r) : "f"(x));
    return __uint_as_float(r);
}

__device__ __forceinline__ void mma_tf32(float* c,
    unsigned a0, unsigned a1, unsigned a2, unsigned a3,
    unsigned b0, unsigned b1)
{
    asm volatile(
        "mma.sync.aligned.m16n8k8.row.col.f32.tf32.tf32.f32 "
        "{%0,%1,%2,%3}, {%4,%5,%6,%7}, {%8,%9}, {%0,%1,%2,%3};"
        : "+f"(c[0]), "+f"(c[1]), "+f"(c[2]), "+f"(c[3])
        : "r"(a0), "r"(a1), "r"(a2), "r"(a3), "r"(b0), "r"(b1));
}

__device__ __forceinline__ void cp16(unsigned dst, const void* src) {
    asm volatile("cp.async.cg.shared.global [%0], [%1], 16;" :: "r"(dst), "l"(src));
}
#define CP_COMMIT() asm volatile("cp.async.commit_group;")
#define CP_WAIT(N)  asm volatile("cp.async.wait_group %0;" :: "n"(N))

__device__ __forceinline__ unsigned smem_u32(const void* p) {
    return (unsigned)__cvta_generic_to_shared(p);
}

// ------------------------------------------------------------------
// Prep: tf32-round x, w_qkv, w_proj in ONE launch (grid-stride over
// three concatenated float4 ranges)
// ------------------------------------------------------------------
#define N4_X  (MM*CC/4)
#define N4_WQ (CC*C3/4)
#define N4_WP (CC*CC/4)

__global__ __launch_bounds__(256) void prep_tf32_kernel(
    const float* __restrict__ x, const float* __restrict__ wq,
    const float* __restrict__ wp)
{
    int i = blockIdx.x * blockDim.x + threadIdx.x;
    const float4* src;
    float4* dst;
    int off;
    if (i < N4_X) {
        src = (const float4*)x; dst = (float4*)g_xt; off = i;
    } else if (i < N4_X + N4_WQ) {
        src = (const float4*)wq; dst = (float4*)g_wq; off = i - N4_X;
    } else if (i < N4_X + N4_WQ + N4_WP) {
        src = (const float4*)wp; dst = (float4*)g_wp; off = i - N4_X - N4_WQ;
    } else return;
    float4 v = src[off];
    v.x = f2tf32(v.x); v.y = f2tf32(v.y); v.z = f2tf32(v.z); v.w = f2tf32(v.w);
    dst[off] = v;
}

// ------------------------------------------------------------------
// RoPE cos/sin table, angles in float64 (matches numpy reference)
// ------------------------------------------------------------------
__global__ __launch_bounds__(256) void rope_table_kernel()
{
    int idx = blockIdx.x * blockDim.x + threadIdx.x;
    if (idx >= TT * 32) return;
    int t = idx >> 5, i = idx & 31;
    double invf = exp(-(double)i / 32.0 * 9.210340371976184);  // ln(10000)
    double da = (double)t * invf;
    g_cos[idx] = (float)cos(da);
    g_sin[idx] = (float)sin(da);
}

// ------------------------------------------------------------------
// RoPE + split: qkv[B,T,3C] -> q,k,v[B,H,T,D], tf32-rounded outputs
// ------------------------------------------------------------------
__global__ __launch_bounds__(256) void rope_split_kernel()
{
    const long long idx = (long long)blockIdx.x * blockDim.x + threadIdx.x;
    if (idx >= (long long)BB * HH * TT * DD) return;

    const int d = (int)(idx & 63);
    const int t = (int)((idx >> 6) & 2047);
    const int h = (int)((idx >> 17) & 15);
    const int b = (int)(idx >> 21);

    const size_t base = ((size_t)(b * TT + t)) * C3 + h * DD;
    const int d2 = d ^ 32;

    const float qv = g_qkv[base + d];
    const float qp = g_qkv[base + d2];
    const float kv = g_qkv[base + CC + d];
    const float kp = g_qkv[base + CC + d2];
    const float vv = g_qkv[base + 2 * CC + d];

    const float qrot = (d < 32) ? -qp : qp;
    const float krot = (d < 32) ? -kp : kp;

    const int ti = (t << 5) + (d & 31);
    const float cs = g_cos[ti];
    const float sn = g_sin[ti];

    const size_t oidx = (((size_t)(b * HH + h)) * TT + t) * DD + d;
    g_q[oidx] = f2tf32(qv * cs + qrot * sn);
    g_k[oidx] = f2tf32(kv * cs + krot * sn);
    g_v[oidx] = f2tf32(vv);
}

// ------------------------------------------------------------------
// TF32 GEMM, 4-stage cp.async pipeline (unchanged from R3).
// ------------------------------------------------------------------
#define STG 4
#define ASTR 20
#define BSTR 136
#define GA_TILE (128*ASTR)
#define GB_TILE (16*BSTR)

__global__ __launch_bounds__(256, 2) void gemm_pipe(
    const float* __restrict__ A, const float* __restrict__ B,
    float* __restrict__ C, int M, int N, int K)
{
    extern __shared__ float sm[];
    float* As = sm;
    float* Bs = sm + STG * GA_TILE;

    const int tid  = threadIdx.x;
    const int lane = tid & 31;
    const int wid  = tid >> 5;
    const int wm   = (wid >> 2) << 6;
    const int wn   = (wid & 3) << 5;
    const int lq   = lane >> 2;
    const int lr   = lane & 3;
    const int row0 = blockIdx.y * 128;
    const int col0 = blockIdx.x * 128;

    const int a_row = tid >> 2;
    const int a_col = (tid & 3) << 2;
    const int b_row = tid >> 5;
    const int b_col = (tid & 31) << 2;

    const unsigned sA = smem_u32(As);
    const unsigned sB = smem_u32(Bs);
    const int KT = K >> 4;

    float acc[4][4][4];
    #pragma unroll
    for (int i = 0; i < 4; i++)
        #pragma unroll
        for (int j = 0; j < 4; j++)
            #pragma unroll
            for (int v = 0; v < 4; v++) acc[i][j][v] = 0.f;

    #define GEMM_ISSUE(kt, st) do {                                            \
        const float* a0p = A + (size_t)(row0 + a_row) * K + ((kt) << 4) + a_col;\
        const float* a1p = a0p + (size_t)64 * K;                                \
        cp16(sA + (unsigned)((st)*GA_TILE + a_row*ASTR + a_col) * 4u, a0p);     \
        cp16(sA + (unsigned)((st)*GA_TILE + (a_row+64)*ASTR + a_col) * 4u, a1p);\
        const float* b0p = B + (size_t)(((kt) << 4) + b_row) * N + col0 + b_col;\
        const float* b1p = b0p + (size_t)8 * N;                                 \
        cp16(sB + (unsigned)((st)*GB_TILE + b_row*BSTR + b_col) * 4u, b0p);     \
        cp16(sB + (unsigned)((st)*GB_TILE + (b_row+8)*BSTR + b_col) * 4u, b1p); \
        CP_COMMIT();                                                            \
    } while (0)

    GEMM_ISSUE(0, 0);
    GEMM_ISSUE(1, 1);
    GEMM_ISSUE(2, 2);

    for (int kt = 0; kt < KT; kt++) {
        const int rem = KT - 1 - kt;
        if (rem >= 2)      CP_WAIT(2);
        else if (rem == 1) CP_WAIT(1);
        else               CP_WAIT(0);
        __syncthreads();
        if (kt + 3 < KT) GEMM_ISSUE(kt + 3, (kt + 3) & 3);

        const float* At = As + (kt & 3) * GA_TILE;
        const float* Bt = Bs + (kt & 3) * GB_TILE;

        #pragma unroll
        for (int kb = 0; kb < 16; kb += 8) {
            unsigned aF[4][4], bF[4][2];
            #pragma unroll
            for (int mi = 0; mi < 4; mi++) {
                const float* ap = At + (wm + (mi << 4) + lq) * ASTR + kb + lr;
                aF[mi][0] = __float_as_uint(ap[0]);
                aF[mi][1] = __float_as_uint(ap[8 * ASTR]);
                aF[mi][2] = __float_as_uint(ap[4]);
                aF[mi][3] = __float_as_uint(ap[8 * ASTR + 4]);
            }
            #pragma unroll
            for (int nj = 0; nj < 4; nj++) {
                const float* bp = Bt + (kb + lr) * BSTR + wn + (nj << 3) + lq;
                bF[nj][0] = __float_as_uint(bp[0]);
                bF[nj][1] = __float_as_uint(bp[4 * BSTR]);
            }
            #pragma unroll
            for (int mi = 0; mi < 4; mi++)
                #pragma unroll
                for (int nj = 0; nj < 4; nj++)
                    mma_tf32(acc[mi][nj], aF[mi][0], aF[mi][1], aF[mi][2], aF[mi][3],
                             bF[nj][0], bF[nj][1]);
        }
    }

    #pragma unroll
    for (int mi = 0; mi < 4; mi++) {
        const int r = row0 + wm + (mi << 4) + lq;
        #pragma unroll
        for (int nj = 0; nj < 4; nj++) {
            const int cc = col0 + wn + (nj << 3) + (lr << 1);
            *(float2*)(C + (size_t)r * N + cc)       = make_float2(acc[mi][nj][0], acc[mi][nj][1]);
            *(float2*)(C + (size_t)(r + 8) * N + cc) = make_float2(acc[mi][nj][2], acc[mi][nj][3]);
        }
    }
    #undef GEMM_ISSUE
}

// ------------------------------------------------------------------
// Flash attention: 128-query tile, 256 threads (8 warps), tf32 mma,
// cp.async double-buffered 64-key K/V tiles. Causal.
// ------------------------------------------------------------------
#define QSTR 68
#define KSTR 68
#define VSTR 72

__global__ __launch_bounds__(256) void attn_pipe(
    const float* __restrict__ Q, const float* __restrict__ K,
    const float* __restrict__ V)
{
    extern __shared__ float sm[];
    float* Qs = sm;                       // [128][QSTR]
    float* Ks = Qs + 128 * QSTR;          // [2][64][KSTR]
    float* Vs = Ks + 2 * 64 * KSTR;       // [2][64][VSTR] natural [key][d]
    float* Ps = Vs + 2 * 64 * VSTR;       // [128][QSTR]

    const int tid  = threadIdx.x;
    const int lane = tid & 31;
    const int wid  = tid >> 5;
    const int wq   = wid << 4;            // 0..112
    const int lq   = lane >> 2;
    const int lr   = lane & 3;

    const int qt = gridDim.x - 1 - blockIdx.x;   // heavy tiles first
    const int bh = blockIdx.y;
    const int q0 = qt << 7;                      // 128-query tile
    const int b = bh >> 4, h = bh & 15;

    const float* Qb = Q + (size_t)bh * TT * DD;
    const float* Kb = K + (size_t)bh * TT * DD;
    const float* Vb = V + (size_t)bh * TT * DD;

    const unsigned sK = smem_u32(Ks);
    const unsigned sV = smem_u32(Vs);

    // 64x64 K/V tile = 1024 float4; 256 threads -> 4 each
    #define ATTN_ISSUE(kt, buf) do {                                           \
        const float* Kp = Kb + (size_t)((kt) << 6) * DD;                        \
        const float* Vp = Vb + (size_t)((kt) << 6) * DD;                        \
        _Pragma("unroll")                                                       \
        for (int i_ = 0; i_ < 4; i_++) {                                        \
            int c_ = tid + (i_ << 8);                                           \
            int r_ = c_ >> 4, co_ = (c_ & 15) << 2;                             \
            cp16(sK + (unsigned)((buf)*64*KSTR + r_*KSTR + co_) * 4u, Kp + r_*DD + co_); \
            cp16(sV + (unsigned)((buf)*64*VSTR + r_*VSTR + co_) * 4u, Vp + r_*DD + co_); \
        }                                                                       \
        CP_COMMIT();                                                            \
    } while (0)

    ATTN_ISSUE(0, 0);

    // Q tile 128x64 = 2048 float4; 8 per thread
    #pragma unroll
    for (int i = 0; i < 8; i++) {
        int c = tid + (i << 8);
        int row = c >> 4, col = (c & 15) << 2;
        *(float4*)(Qs + row * QSTR + col) = *(const float4*)(Qb + (size_t)(q0 + row) * DD + col);
    }

    float m_lo = -INFINITY, m_hi = -INFINITY;
    float l_lo = 0.f, l_hi = 0.f;
    float oc[8][4];
    #pragma unroll
    for (int nt = 0; nt < 8; nt++)
        #pragma unroll
        for (int v = 0; v < 4; v++) oc[nt][v] = 0.f;

    const int qrow = wq + lq;
    const int row_lo_g = q0 + qrow;       // global query index (lo)
    const int ktmax = (qt << 1) + 1;      // keys up to q0+127

    for (int kt = 0; kt <= ktmax; kt++) {
        CP_WAIT(0);
        __syncthreads();
        if (kt < ktmax) ATTN_ISSUE(kt + 1, (kt + 1) & 1);

        const float* Kt = Ks + (kt & 1) * 64 * KSTR;
        const float* Vt = Vs + (kt & 1) * 64 * VSTR;
        const int k0 = kt << 6;

        // S = Q @ K^T
        float sc[8][4];
        #pragma unroll
        for (int nt = 0; nt < 8; nt++)
            #pragma unroll
            for (int v = 0; v < 4; v++) sc[nt][v] = 0.f;

        #pragma unroll
        for (int ks = 0; ks < 8; ks++) {
            const int kk = (ks << 3) + lr;
            unsigned a0 = __float_as_uint(Qs[qrow * QSTR + kk]);
            unsigned a1 = __float_as_uint(Qs[(qrow + 8) * QSTR + kk]);
            unsigned a2 = __float_as_uint(Qs[qrow * QSTR + kk + 4]);
            unsigned a3 = __float_as_uint(Qs[(qrow + 8) * QSTR + kk + 4]);
            #pragma unroll
            for (int nt = 0; nt < 8; nt++) {
                const int key = (nt << 3) + lq;
                unsigned b0 = __float_as_uint(Kt[key * KSTR + kk]);
                unsigned b1 = __float_as_uint(Kt[key * KSTR + kk + 4]);
                mma_tf32(sc[nt], a0, a1, a2, a3, b0, b1);
            }
        }

        // scale + causal mask (diagonal band tiles) + row max
        float mt_lo = -INFINITY, mt_hi = -INFINITY;
        if (kt >= (qt << 1)) {
            #pragma unroll
            for (int nt = 0; nt < 8; nt++) {
                const int col_g = k0 + (nt << 3) + (lr << 1);
                sc[nt][0] = (col_g     <= row_lo_g)     ? sc[nt][0] * 0.125f : -INFINITY;
                sc[nt][1] = (col_g + 1 <= row_lo_g)     ? sc[nt][1] * 0.125f : -INFINITY;
                sc[nt][2] = (col_g     <= row_lo_g + 8) ? sc[nt][2] * 0.125f : -INFINITY;
                sc[nt][3] = (col_g + 1 <= row_lo_g + 8) ? sc[nt][3] * 0.125f : -INFINITY;
                mt_lo = fmaxf(mt_lo, fmaxf(sc[nt][0], sc[nt][1]));
                mt_hi = fmaxf(mt_hi, fmaxf(sc[nt][2], sc[nt][3]));
            }
        } else {
            #pragma unroll
            for (int nt = 0; nt < 8; nt++) {
                sc[nt][0] *= 0.125f; sc[nt][1] *= 0.125f;
                sc[nt][2] *= 0.125f; sc[nt][3] *= 0.125f;
                mt_lo = fmaxf(mt_lo, fmaxf(sc[nt][0], sc[nt][1]));
                mt_hi = fmaxf(mt_hi, fmaxf(sc[nt][2], sc[nt][3]));
            }
        }
        mt_lo = fmaxf(mt_lo, __shfl_xor_sync(0xffffffffu, mt_lo, 1));
        mt_lo = fmaxf(mt_lo, __shfl_xor_sync(0xffffffffu, mt_lo, 2));
        mt_hi = fmaxf(mt_hi, __shfl_xor_sync(0xffffffffu, mt_hi, 1));
        mt_hi = fmaxf(mt_hi, __shfl_xor_sync(0xffffffffu, mt_hi, 2));

        const float mn_lo = fmaxf(m_lo, mt_lo);
        const float mn_hi = fmaxf(m_hi, mt_hi);
        const float al_lo = __expf(m_lo - mn_lo);
        const float al_hi = __expf(m_hi - mn_hi);

        float ls_lo = 0.f, ls_hi = 0.f;
        #pragma unroll
        for (int nt = 0; nt < 8; nt++) {
            sc[nt][0] = __expf(sc[nt][0] - mn_lo);
            sc[nt][1] = __expf(sc[nt][1] - mn_lo);
            sc[nt][2] = __expf(sc[nt][2] - mn_hi);
            sc[nt][3] = __expf(sc[nt][3] - mn_hi);
            ls_lo += sc[nt][0] + sc[nt][1];
            ls_hi += sc[nt][2] + sc[nt][3];
        }
        ls_lo += __shfl_xor_sync(0xffffffffu, ls_lo, 1);
        ls_lo += __shfl_xor_sync(0xffffffffu, ls_lo, 2);
        ls_hi += __shfl_xor_sync(0xffffffffu, ls_hi, 1);
        ls_hi += __shfl_xor_sync(0xffffffffu, ls_hi, 2);

        l_lo = l_lo * al_lo + ls_lo;
        l_hi = l_hi * al_hi + ls_hi;
        m_lo = mn_lo; m_hi = mn_hi;

        #pragma unroll
        for (int nt = 0; nt < 8; nt++) {
            oc[nt][0] *= al_lo; oc[nt][1] *= al_lo;
            oc[nt][2] *= al_hi; oc[nt][3] *= al_hi;
        }

        // stage P (tf32) — warp-private rows
        #pragma unroll
        for (int nt = 0; nt < 8; nt++) {
            const int col = (nt << 3) + (lr << 1);
            *(float2*)(Ps + qrow * QSTR + col) =
                make_float2(f2tf32(sc[nt][0]), f2tf32(sc[nt][1]));
            *(float2*)(Ps + (qrow + 8) * QSTR + col) =
                make_float2(f2tf32(sc[nt][2]), f2tf32(sc[nt][3]));
        }
        __syncwarp();

        // O += P @ V  (V natural [key][d])
        #pragma unroll
        for (int ks = 0; ks < 8; ks++) {
            const int kk = (ks << 3) + lr;
            unsigned a0 = __float_as_uint(Ps[qrow * QSTR + kk]);
            unsigned a1 = __float_as_uint(Ps[(qrow + 8) * QSTR + kk]);
            unsigned a2 = __float_as_uint(Ps[qrow * QSTR + kk + 4]);
            unsigned a3 = __float_as_uint(Ps[(qrow + 8) * QSTR + kk + 4]);
            #pragma unroll
            for (int nt = 0; nt < 8; nt++) {
                const int dd = (nt << 3) + lq;
                unsigned b0 = __float_as_uint(Vt[kk * VSTR + dd]);
                unsigned b1 = __float_as_uint(Vt[(kk + 4) * VSTR + dd]);
                mma_tf32(oc[nt], a0, a1, a2, a3, b0, b1);
            }
        }
    }

    // epilogue
    const float inv_lo = 1.f / l_lo;
    const float inv_hi = 1.f / l_hi;
    const int t_lo = q0 + qrow;
    float* out_lo = g_y + ((size_t)(b * TT + t_lo)) * CC + h * DD;
    float* out_hi = g_y + ((size_t)(b * TT + t_lo + 8)) * CC + h * DD;
    #pragma unroll
    for (int nt = 0; nt < 8; nt++) {
        const int col = (nt << 3) + (lr << 1);
        *(float2*)(out_lo + col) = make_float2(f2tf32(oc[nt][0] * inv_lo), f2tf32(oc[nt][1] * inv_lo));
        *(float2*)(out_hi + col) = make_float2(f2tf32(oc[nt][2] * inv_hi), f2tf32(oc[nt][3] * inv_hi));
    }
    #undef ATTN_ISSUE
}

// ------------------------------------------------------------------
// Launch
// ------------------------------------------------------------------
extern "C" void kernel_launch(void* const* d_in, const int* in_sizes, int n_in,
                              void* d_out, int out_size)
{
    const float* x      = (const float*)d_in[0];
    const float* w_qkv  = (const float*)d_in[1];
    const float* w_proj = (const float*)d_in[2];
    float* out = (float*)d_out;

    float *p_qkv, *p_q, *p_k, *p_v, *p_y, *p_xt, *p_wq, *p_wp;
    cudaGetSymbolAddress((void**)&p_qkv, g_qkv);
    cudaGetSymbolAddress((void**)&p_q, g_q);
    cudaGetSymbolAddress((void**)&p_k, g_k);
    cudaGetSymbolAddress((void**)&p_v, g_v);
    cudaGetSymbolAddress((void**)&p_y, g_y);
    cudaGetSymbolAddress((void**)&p_xt, g_xt);
    cudaGetSymbolAddress((void**)&p_wq, g_wq);
    cudaGetSymbolAddress((void**)&p_wp, g_wp);

    // 0. prep (one launch) + rope table
    {
        const int total4 = N4_X + N4_WQ + N4_WP;
        prep_tf32_kernel<<<(total4 + 255)/256, 256>>>(x, w_qkv, w_proj);
        rope_table_kernel<<<(TT*32 + 255)/256, 256>>>();
    }

    const int gemm_smem = STG * (GA_TILE + GB_TILE) * (int)sizeof(float);
    cudaFuncSetAttribute(gemm_pipe,
                         cudaFuncAttributeMaxDynamicSharedMemorySize, gemm_smem);

    // 1. qkv = xt @ wq
    {
        dim3 grid(C3 / 128, MM / 128);
        gemm_pipe<<<grid, 256, gemm_smem>>>(p_xt, p_wq, p_qkv, MM, C3, CC);
    }

    // 2. rope + split (tf32 outputs)
    {
        long long n = (long long)BB * HH * TT * DD;
        rope_split_kernel<<<(int)((n + 255) / 256), 256>>>();
    }

    // 3. attention (128-query tiles, 8 warps)
    {
        const int smem = (128*QSTR + 2*64*KSTR + 2*64*VSTR + 128*QSTR) * (int)sizeof(float); // 141312
        cudaFuncSetAttribute(attn_pipe,
                             cudaFuncAttributeMaxDynamicSharedMemorySize, smem);
        dim3 grid(TT / 128, BB * HH);
        attn_pipe<<<grid, 256, smem>>>(p_q, p_k, p_v);
    }

    // 4. out = y @ wp
    {
        dim3 grid(CC / 128, MM / 128);
        gemm_pipe<<<grid, 256, gemm_smem>>>(p_y, p_wp, out, MM, CC, CC);
    }
}

// round 5
// speedup vs baseline: 1.0102x; 1.0102x over previous
#include <cuda_runtime.h>
#include <cuda_bf16.h>
#include <math.h>

// Problem constants: B=4, T=2048, C=1024, H=16, D=64
#define BB 4
#define TT 2048
#define CC 1024
#define HH 16
#define DD 64
#define MM (BB*TT)        // 8192
#define C3 (3*CC)         // 3072

// ------------------------------------------------------------------
// Scratch
// ------------------------------------------------------------------
__device__ float g_qkv[(size_t)MM*C3];     // [B,T,3C] fp32
__device__ float g_q[(size_t)MM*CC];       // [B,H,T,D] roped, tf32
__device__ float g_k[(size_t)MM*CC];       // [B,H,T,D] roped, tf32
__device__ float g_v[(size_t)MM*CC];       // [B,H,T,D] tf32
__device__ float g_y[(size_t)MM*CC];       // attn out [B,T,C], tf32
__device__ float g_xt[(size_t)MM*CC];      // x rounded to tf32
__device__ float g_wq[(size_t)CC*C3];      // w_qkv tf32
__device__ float g_wp[(size_t)CC*CC];      // w_proj tf32
__device__ float g_cos[TT*32];
__device__ float g_sin[TT*32];

// ------------------------------------------------------------------
// helpers
// ------------------------------------------------------------------
__device__ __forceinline__ float f2tf32(float x) {
    unsigned r;
    asm("cvt.rna.tf32.f32 %0, %1;" : "=r"(r) : "f"(x));
    return __uint_as_float(r);
}

__device__ __forceinline__ void mma_tf32(float* c,
    unsigned a0, unsigned a1, unsigned a2, unsigned a3,
    unsigned b0, unsigned b1)
{
    asm volatile(
        "mma.sync.aligned.m16n8k8.row.col.f32.tf32.tf32.f32 "
        "{%0,%1,%2,%3}, {%4,%5,%6,%7}, {%8,%9}, {%0,%1,%2,%3};"
        : "+f"(c[0]), "+f"(c[1]), "+f"(c[2]), "+f"(c[3])
        : "r"(a0), "r"(a1), "r"(a2), "r"(a3), "r"(b0), "r"(b1));
}

__device__ __forceinline__ void cp16(unsigned dst, const void* src) {
    asm volatile("cp.async.cg.shared.global [%0], [%1], 16;" :: "r"(dst), "l"(src));
}
#define CP_COMMIT() asm volatile("cp.async.commit_group;")
#define CP_WAIT(N)  asm volatile("cp.async.wait_group %0;" :: "n"(N))

__device__ __forceinline__ unsigned smem_u32(const void* p) {
    return (unsigned)__cvta_generic_to_shared(p);
}

// ------------------------------------------------------------------
// Prep: tf32-round x, w_qkv, w_proj in ONE launch
// ------------------------------------------------------------------
#define N4_X  (MM*CC/4)
#define N4_WQ (CC*C3/4)
#define N4_WP (CC*CC/4)

__global__ __launch_bounds__(256) void prep_tf32_kernel(
    const float* __restrict__ x, const float* __restrict__ wq,
    const float* __restrict__ wp)
{
    int i = blockIdx.x * blockDim.x + threadIdx.x;
    const float4* src;
    float4* dst;
    int off;
    if (i < N4_X) {
        src = (const float4*)x; dst = (float4*)g_xt; off = i;
    } else if (i < N4_X + N4_WQ) {
        src = (const float4*)wq; dst = (float4*)g_wq; off = i - N4_X;
    } else if (i < N4_X + N4_WQ + N4_WP) {
        src = (const float4*)wp; dst = (float4*)g_wp; off = i - N4_X - N4_WQ;
    } else return;
    float4 v = src[off];
    v.x = f2tf32(v.x); v.y = f2tf32(v.y); v.z = f2tf32(v.z); v.w = f2tf32(v.w);
    dst[off] = v;
}

// ------------------------------------------------------------------
// RoPE cos/sin table, angles in float64 (matches numpy reference)
// ------------------------------------------------------------------
__global__ __launch_bounds__(256) void rope_table_kernel()
{
    int idx = blockIdx.x * blockDim.x + threadIdx.x;
    if (idx >= TT * 32) return;
    int t = idx >> 5, i = idx & 31;
    double invf = exp(-(double)i / 32.0 * 9.210340371976184);  // ln(10000)
    double da = (double)t * invf;
    g_cos[idx] = (float)cos(da);
    g_sin[idx] = (float)sin(da);
}

// ------------------------------------------------------------------
// RoPE + split, float4-vectorized: each thread does 4 consecutive d.
// qkv[B,T,3C] -> q,k,v[B,H,T,D], tf32-rounded outputs.
// ------------------------------------------------------------------
__global__ __launch_bounds__(256) void rope_split_kernel()
{
    const int idx = blockIdx.x * blockDim.x + threadIdx.x;   // BB*HH*TT*16
    if (idx >= BB * HH * TT * 16) return;

    const int d4 = idx & 15;               // float4 index within head dim
    const int t  = (idx >> 4) & 2047;
    const int h  = (idx >> 15) & 15;
    const int b  = idx >> 19;
    const int d  = d4 << 2;

    const size_t base = ((size_t)(b * TT + t)) * C3 + h * DD;
    const int dp = d ^ 32;                 // partner block (also float4-aligned)

    const float4 qv = *(const float4*)(g_qkv + base + d);
    const float4 qp = *(const float4*)(g_qkv + base + dp);
    const float4 kv = *(const float4*)(g_qkv + base + CC + d);
    const float4 kp = *(const float4*)(g_qkv + base + CC + dp);
    const float4 vv = *(const float4*)(g_qkv + base + 2 * CC + d);

    const float sgn = (d < 32) ? -1.f : 1.f;
    const int ti = (t << 5) + (d & 31);
    const float4 cs = *(const float4*)(g_cos + ti);
    const float4 sn = *(const float4*)(g_sin + ti);

    float4 qo, ko, vo;
    qo.x = f2tf32(qv.x * cs.x + sgn * qp.x * sn.x);
    qo.y = f2tf32(qv.y * cs.y + sgn * qp.y * sn.y);
    qo.z = f2tf32(qv.z * cs.z + sgn * qp.z * sn.z);
    qo.w = f2tf32(qv.w * cs.w + sgn * qp.w * sn.w);
    ko.x = f2tf32(kv.x * cs.x + sgn * kp.x * sn.x);
    ko.y = f2tf32(kv.y * cs.y + sgn * kp.y * sn.y);
    ko.z = f2tf32(kv.z * cs.z + sgn * kp.z * sn.z);
    ko.w = f2tf32(kv.w * cs.w + sgn * kp.w * sn.w);
    vo.x = f2tf32(vv.x); vo.y = f2tf32(vv.y);
    vo.z = f2tf32(vv.z); vo.w = f2tf32(vv.w);

    const size_t oidx = (((size_t)(b * HH + h)) * TT + t) * DD + d;
    *(float4*)(g_q + oidx) = qo;
    *(float4*)(g_k + oidx) = ko;
    *(float4*)(g_v + oidx) = vo;
}

// ------------------------------------------------------------------
// TF32 GEMM, 4-stage cp.async pipeline (unchanged).
// ------------------------------------------------------------------
#define STG 4
#define ASTR 20
#define BSTR 136
#define GA_TILE (128*ASTR)
#define GB_TILE (16*BSTR)

__global__ __launch_bounds__(256, 2) void gemm_pipe(
    const float* __restrict__ A, const float* __restrict__ B,
    float* __restrict__ C, int M, int N, int K)
{
    extern __shared__ float sm[];
    float* As = sm;
    float* Bs = sm + STG * GA_TILE;

    const int tid  = threadIdx.x;
    const int lane = tid & 31;
    const int wid  = tid >> 5;
    const int wm   = (wid >> 2) << 6;
    const int wn   = (wid & 3) << 5;
    const int lq   = lane >> 2;
    const int lr   = lane & 3;
    const int row0 = blockIdx.y * 128;
    const int col0 = blockIdx.x * 128;

    const int a_row = tid >> 2;
    const int a_col = (tid & 3) << 2;
    const int b_row = tid >> 5;
    const int b_col = (tid & 31) << 2;

    const unsigned sA = smem_u32(As);
    const unsigned sB = smem_u32(Bs);
    const int KT = K >> 4;

    float acc[4][4][4];
    #pragma unroll
    for (int i = 0; i < 4; i++)
        #pragma unroll
        for (int j = 0; j < 4; j++)
            #pragma unroll
            for (int v = 0; v < 4; v++) acc[i][j][v] = 0.f;

    #define GEMM_ISSUE(kt, st) do {                                            \
        const float* a0p = A + (size_t)(row0 + a_row) * K + ((kt) << 4) + a_col;\
        const float* a1p = a0p + (size_t)64 * K;                                \
        cp16(sA + (unsigned)((st)*GA_TILE + a_row*ASTR + a_col) * 4u, a0p);     \
        cp16(sA + (unsigned)((st)*GA_TILE + (a_row+64)*ASTR + a_col) * 4u, a1p);\
        const float* b0p = B + (size_t)(((kt) << 4) + b_row) * N + col0 + b_col;\
        const float* b1p = b0p + (size_t)8 * N;                                 \
        cp16(sB + (unsigned)((st)*GB_TILE + b_row*BSTR + b_col) * 4u, b0p);     \
        cp16(sB + (unsigned)((st)*GB_TILE + (b_row+8)*BSTR + b_col) * 4u, b1p); \
        CP_COMMIT();                                                            \
    } while (0)

    GEMM_ISSUE(0, 0);
    GEMM_ISSUE(1, 1);
    GEMM_ISSUE(2, 2);

    for (int kt = 0; kt < KT; kt++) {
        const int rem = KT - 1 - kt;
        if (rem >= 2)      CP_WAIT(2);
        else if (rem == 1) CP_WAIT(1);
        else               CP_WAIT(0);
        __syncthreads();
        if (kt + 3 < KT) GEMM_ISSUE(kt + 3, (kt + 3) & 3);

        const float* At = As + (kt & 3) * GA_TILE;
        const float* Bt = Bs + (kt & 3) * GB_TILE;

        #pragma unroll
        for (int kb = 0; kb < 16; kb += 8) {
            unsigned aF[4][4], bF[4][2];
            #pragma unroll
            for (int mi = 0; mi < 4; mi++) {
                const float* ap = At + (wm + (mi << 4) + lq) * ASTR + kb + lr;
                aF[mi][0] = __float_as_uint(ap[0]);
                aF[mi][1] = __float_as_uint(ap[8 * ASTR]);
                aF[mi][2] = __float_as_uint(ap[4]);
                aF[mi][3] = __float_as_uint(ap[8 * ASTR + 4]);
            }
            #pragma unroll
            for (int nj = 0; nj < 4; nj++) {
                const float* bp = Bt + (kb + lr) * BSTR + wn + (nj << 3) + lq;
                bF[nj][0] = __float_as_uint(bp[0]);
                bF[nj][1] = __float_as_uint(bp[4 * BSTR]);
            }
            #pragma unroll
            for (int mi = 0; mi < 4; mi++)
                #pragma unroll
                for (int nj = 0; nj < 4; nj++)
                    mma_tf32(acc[mi][nj], aF[mi][0], aF[mi][1], aF[mi][2], aF[mi][3],
                             bF[nj][0], bF[nj][1]);
        }
    }

    #pragma unroll
    for (int mi = 0; mi < 4; mi++) {
        const int r = row0 + wm + (mi << 4) + lq;
        #pragma unroll
        for (int nj = 0; nj < 4; nj++) {
            const int cc = col0 + wn + (nj << 3) + (lr << 1);
            *(float2*)(C + (size_t)r * N + cc)       = make_float2(acc[mi][nj][0], acc[mi][nj][1]);
            *(float2*)(C + (size_t)(r + 8) * N + cc) = make_float2(acc[mi][nj][2], acc[mi][nj][3]);
        }
    }
    #undef GEMM_ISSUE
}

// ------------------------------------------------------------------
// Flash attention: 64-query tile, 128 threads (4 warps), tf32 mma,
// cp.async double-buffered K/V. Q fragments hoisted to registers;
// P overlays the Q smem buffer (warp-private rows -> no hazard).
// ------------------------------------------------------------------
#define QSTR 68
#define KSTR 68
#define VSTR 72

__global__ __launch_bounds__(128) void attn_pipe(
    const float* __restrict__ Q, const float* __restrict__ K,
    const float* __restrict__ V)
{
    extern __shared__ float sm[];
    float* QP = sm;                       // [64][QSTR]  Q tile, then P tile
    float* Ks = QP + 64 * QSTR;           // [2][64][KSTR]
    float* Vs = Ks + 2 * 64 * KSTR;       // [2][64][VSTR] natural [key][d]

    const int tid  = threadIdx.x;
    const int lane = tid & 31;
    const int wid  = tid >> 5;
    const int wq   = wid << 4;
    const int lq   = lane >> 2;
    const int lr   = lane & 3;

    const int qt = gridDim.x - 1 - blockIdx.x;   // heavy tiles first
    const int bh = blockIdx.y;
    const int q0 = qt << 6;
    const int b = bh >> 4, h = bh & 15;

    const float* Qb = Q + (size_t)bh * TT * DD;
    const float* Kb = K + (size_t)bh * TT * DD;
    const float* Vb = V + (size_t)bh * TT * DD;

    const unsigned sK = smem_u32(Ks);
    const unsigned sV = smem_u32(Vs);

    #define ATTN_ISSUE(kt, buf) do {                                           \
        const float* Kp = Kb + (size_t)((kt) << 6) * DD;                        \
        const float* Vp = Vb + (size_t)((kt) << 6) * DD;                        \
        _Pragma("unroll")                                                       \
        for (int i_ = 0; i_ < 8; i_++) {                                        \
            int c_ = tid + (i_ << 7);                                           \
            int r_ = c_ >> 4, co_ = (c_ & 15) << 2;                             \
            cp16(sK + (unsigned)((buf)*64*KSTR + r_*KSTR + co_) * 4u, Kp + r_*DD + co_); \
            cp16(sV + (unsigned)((buf)*64*VSTR + r_*VSTR + co_) * 4u, Vp + r_*DD + co_); \
        }                                                                       \
        CP_COMMIT();                                                            \
    } while (0)

    ATTN_ISSUE(0, 0);

    // Q tile into QP
    #pragma unroll
    for (int i = 0; i < 8; i++) {
        int c = tid + (i << 7);
        int row = c >> 4, col = (c & 15) << 2;
        *(float4*)(QP + row * QSTR + col) = *(const float4*)(Qb + (size_t)(q0 + row) * DD + col);
    }
    __syncthreads();

    // Hoist Q mma fragments (loop-invariant). Warp reads only its own rows.
    const int qrow = wq + lq;
    unsigned qa[8][4];
    #pragma unroll
    for (int ks = 0; ks < 8; ks++) {
        const int kk = (ks << 3) + lr;
        qa[ks][0] = __float_as_uint(QP[qrow * QSTR + kk]);
        qa[ks][1] = __float_as_uint(QP[(qrow + 8) * QSTR + kk]);
        qa[ks][2] = __float_as_uint(QP[qrow * QSTR + kk + 4]);
        qa[ks][3] = __float_as_uint(QP[(qrow + 8) * QSTR + kk + 4]);
    }
    // From here on QP serves as the P tile; each warp touches only
    // rows [wq, wq+16) for both reads and writes -> no cross-warp hazard.

    float m_lo = -INFINITY, m_hi = -INFINITY;
    float l_lo = 0.f, l_hi = 0.f;
    float oc[8][4];
    #pragma unroll
    for (int nt = 0; nt < 8; nt++)
        #pragma unroll
        for (int v = 0; v < 4; v++) oc[nt][v] = 0.f;

    for (int kt = 0; kt <= qt; kt++) {
        CP_WAIT(0);
        __syncthreads();
        if (kt < qt) ATTN_ISSUE(kt + 1, (kt + 1) & 1);

        const float* Kt = Ks + (kt & 1) * 64 * KSTR;
        const float* Vt = Vs + (kt & 1) * 64 * VSTR;

        // S = Q @ K^T
        float sc[8][4];
        #pragma unroll
        for (int nt = 0; nt < 8; nt++)
            #pragma unroll
            for (int v = 0; v < 4; v++) sc[nt][v] = 0.f;

        #pragma unroll
        for (int ks = 0; ks < 8; ks++) {
            const int kk = (ks << 3) + lr;
            #pragma unroll
            for (int nt = 0; nt < 8; nt++) {
                const int key = (nt << 3) + lq;
                unsigned b0 = __float_as_uint(Kt[key * KSTR + kk]);
                unsigned b1 = __float_as_uint(Kt[key * KSTR + kk + 4]);
                mma_tf32(sc[nt], qa[ks][0], qa[ks][1], qa[ks][2], qa[ks][3], b0, b1);
            }
        }

        // scale + causal mask + row max
        float mt_lo = -INFINITY, mt_hi = -INFINITY;
        const int row_lo = wq + lq;
        const int row_hi = row_lo + 8;
        if (kt == qt) {
            #pragma unroll
            for (int nt = 0; nt < 8; nt++) {
                const int col = (nt << 3) + (lr << 1);
                sc[nt][0] = (col     <= row_lo) ? sc[nt][0] * 0.125f : -INFINITY;
                sc[nt][1] = (col + 1 <= row_lo) ? sc[nt][1] * 0.125f : -INFINITY;
                sc[nt][2] = (col     <= row_hi) ? sc[nt][2] * 0.125f : -INFINITY;
                sc[nt][3] = (col + 1 <= row_hi) ? sc[nt][3] * 0.125f : -INFINITY;
                mt_lo = fmaxf(mt_lo, fmaxf(sc[nt][0], sc[nt][1]));
                mt_hi = fmaxf(mt_hi, fmaxf(sc[nt][2], sc[nt][3]));
            }
        } else {
            #pragma unroll
            for (int nt = 0; nt < 8; nt++) {
                sc[nt][0] *= 0.125f; sc[nt][1] *= 0.125f;
                sc[nt][2] *= 0.125f; sc[nt][3] *= 0.125f;
                mt_lo = fmaxf(mt_lo, fmaxf(sc[nt][0], sc[nt][1]));
                mt_hi = fmaxf(mt_hi, fmaxf(sc[nt][2], sc[nt][3]));
            }
        }
        mt_lo = fmaxf(mt_lo, __shfl_xor_sync(0xffffffffu, mt_lo, 1));
        mt_lo = fmaxf(mt_lo, __shfl_xor_sync(0xffffffffu, mt_lo, 2));
        mt_hi = fmaxf(mt_hi, __shfl_xor_sync(0xffffffffu, mt_hi, 1));
        mt_hi = fmaxf(mt_hi, __shfl_xor_sync(0xffffffffu, mt_hi, 2));

        const float mn_lo = fmaxf(m_lo, mt_lo);
        const float mn_hi = fmaxf(m_hi, mt_hi);
        const float al_lo = __expf(m_lo - mn_lo);
        const float al_hi = __expf(m_hi - mn_hi);

        float ls_lo = 0.f, ls_hi = 0.f;
        #pragma unroll
        for (int nt = 0; nt < 8; nt++) {
            sc[nt][0] = __expf(sc[nt][0] - mn_lo);
            sc[nt][1] = __expf(sc[nt][1] - mn_lo);
            sc[nt][2] = __expf(sc[nt][2] - mn_hi);
            sc[nt][3] = __expf(sc[nt][3] - mn_hi);
            ls_lo += sc[nt][0] + sc[nt][1];
            ls_hi += sc[nt][2] + sc[nt][3];
        }
        ls_lo += __shfl_xor_sync(0xffffffffu, ls_lo, 1);
        ls_lo += __shfl_xor_sync(0xffffffffu, ls_lo, 2);
        ls_hi += __shfl_xor_sync(0xffffffffu, ls_hi, 1);
        ls_hi += __shfl_xor_sync(0xffffffffu, ls_hi, 2);

        l_lo = l_lo * al_lo + ls_lo;
        l_hi = l_hi * al_hi + ls_hi;
        m_lo = mn_lo; m_hi = mn_hi;

        #pragma unroll
        for (int nt = 0; nt < 8; nt++) {
            oc[nt][0] *= al_lo; oc[nt][1] *= al_lo;
            oc[nt][2] *= al_hi; oc[nt][3] *= al_hi;
        }

        // stage P (tf32) into warp-private rows of QP
        #pragma unroll
        for (int nt = 0; nt < 8; nt++) {
            const int col = (nt << 3) + (lr << 1);
            *(float2*)(QP + qrow * QSTR + col) =
                make_float2(f2tf32(sc[nt][0]), f2tf32(sc[nt][1]));
            *(float2*)(QP + (qrow + 8) * QSTR + col) =
                make_float2(f2tf32(sc[nt][2]), f2tf32(sc[nt][3]));
        }
        __syncwarp();

        // O += P @ V  (V natural [key][d])
        #pragma unroll
        for (int ks = 0; ks < 8; ks++) {
            const int kk = (ks << 3) + lr;
            unsigned a0 = __float_as_uint(QP[qrow * QSTR + kk]);
            unsigned a1 = __float_as_uint(QP[(qrow + 8) * QSTR + kk]);
            unsigned a2 = __float_as_uint(QP[qrow * QSTR + kk + 4]);
            unsigned a3 = __float_as_uint(QP[(qrow + 8) * QSTR + kk + 4]);
            #pragma unroll
            for (int nt = 0; nt < 8; nt++) {
                const int dd = (nt << 3) + lq;
                unsigned b0 = __float_as_uint(Vt[kk * VSTR + dd]);
                unsigned b1 = __float_as_uint(Vt[(kk + 4) * VSTR + dd]);
                mma_tf32(oc[nt], a0, a1, a2, a3, b0, b1);
            }
        }
    }

    // epilogue
    const float inv_lo = 1.f / l_lo;
    const float inv_hi = 1.f / l_hi;
    const int t_lo = q0 + qrow;
    float* out_lo = g_y + ((size_t)(b * TT + t_lo)) * CC + h * DD;
    float* out_hi = g_y + ((size_t)(b * TT + t_lo + 8)) * CC + h * DD;
    #pragma unroll
    for (int nt = 0; nt < 8; nt++) {
        const int col = (nt << 3) + (lr << 1);
        *(float2*)(out_lo + col) = make_float2(f2tf32(oc[nt][0] * inv_lo), f2tf32(oc[nt][1] * inv_lo));
        *(float2*)(out_hi + col) = make_float2(f2tf32(oc[nt][2] * inv_hi), f2tf32(oc[nt][3] * inv_hi));
    }
    #undef ATTN_ISSUE
}

// ------------------------------------------------------------------
// Launch
// ------------------------------------------------------------------
extern "C" void kernel_launch(void* const* d_in, const int* in_sizes, int n_in,
                              void* d_out, int out_size)
{
    const float* x      = (const float*)d_in[0];
    const float* w_qkv  = (const float*)d_in[1];
    const float* w_proj = (const float*)d_in[2];
    float* out = (float*)d_out;

    float *p_qkv, *p_q, *p_k, *p_v, *p_y, *p_xt, *p_wq, *p_wp;
    cudaGetSymbolAddress((void**)&p_qkv, g_qkv);
    cudaGetSymbolAddress((void**)&p_q, g_q);
    cudaGetSymbolAddress((void**)&p_k, g_k);
    cudaGetSymbolAddress((void**)&p_v, g_v);
    cudaGetSymbolAddress((void**)&p_y, g_y);
    cudaGetSymbolAddress((void**)&p_xt, g_xt);
    cudaGetSymbolAddress((void**)&p_wq, g_wq);
    cudaGetSymbolAddress((void**)&p_wp, g_wp);

    // 0. prep (one launch) + rope table
    {
        const int total4 = N4_X + N4_WQ + N4_WP;
        prep_tf32_kernel<<<(total4 + 255)/256, 256>>>(x, w_qkv, w_proj);
        rope_table_kernel<<<(TT*32 + 255)/256, 256>>>();
    }

    const int gemm_smem = STG * (GA_TILE + GB_TILE) * (int)sizeof(float);
    cudaFuncSetAttribute(gemm_pipe,
                         cudaFuncAttributeMaxDynamicSharedMemorySize, gemm_smem);

    // 1. qkv = xt @ wq
    {
        dim3 grid(C3 / 128, MM / 128);
        gemm_pipe<<<grid, 256, gemm_smem>>>(p_xt, p_wq, p_qkv, MM, C3, CC);
    }

    // 2. rope + split (float4 vectorized, tf32 outputs)
    {
        const int n = BB * HH * TT * 16;
        rope_split_kernel<<<(n + 255) / 256, 256>>>();
    }

    // 3. attention (64-query tiles, 4 warps, 2 CTA/SM)
    {
        const int smem = (64*QSTR + 2*64*KSTR + 2*64*VSTR) * (int)sizeof(float); // 89088
        cudaFuncSetAttribute(attn_pipe,
                             cudaFuncAttributeMaxDynamicSharedMemorySize, smem);
        dim3 grid(TT / 64, BB * HH);
        attn_pipe<<<grid, 128, smem>>>(p_q, p_k, p_v);
    }

    // 4. out = y @ wp
    {
        dim3 grid(CC / 128, MM / 128);
        gemm_pipe<<<grid, 256, gemm_smem>>>(p_y, p_wp, out, MM, CC, CC);
    }
}